// round 6
// baseline (speedup 1.0000x reference)
#include <cuda_runtime.h>
#include <cuda_bf16.h>

#define NROWS 8192
#define DIM   128
#define MARGIN 0.2f

#define BM 128
#define BN 128
#define PAD 132          // row stride in floats; 132*4=528 bytes, 16B aligned per k-row
#define NTILES 64        // 8192/128
#define SMEM_BYTES (2 * DIM * PAD * 4)

// Scratch (no allocations allowed in kernel_launch)
__device__ float g_a[NROWS];            // yy[i] - 2*<x_i,y_i> + margin
__device__ float g_b[NROWS];            // yy[j]
__device__ float g_part[NTILES * NTILES];

// ---------------------------------------------------------------------------
// Precompute a[i], b[i]. One warp per row; each lane loads one float4 (4 elems).
// ---------------------------------------------------------------------------
__global__ void precompute_kernel(const float* __restrict__ x,
                                  const float* __restrict__ y) {
    int row  = blockIdx.x * 8 + (threadIdx.x >> 5);
    int lane = threadIdx.x & 31;

    float4 xv = reinterpret_cast<const float4*>(x + (size_t)row * DIM)[lane];
    float4 yv = reinterpret_cast<const float4*>(y + (size_t)row * DIM)[lane];

    float yy  = yv.x * yv.x + yv.y * yv.y + yv.z * yv.z + yv.w * yv.w;
    float dxy = xv.x * yv.x + xv.y * yv.y + xv.z * yv.z + xv.w * yv.w;

    #pragma unroll
    for (int off = 16; off > 0; off >>= 1) {
        yy  += __shfl_xor_sync(0xFFFFFFFFu, yy,  off);
        dxy += __shfl_xor_sync(0xFFFFFFFFu, dxy, off);
    }
    if (lane == 0) {
        g_b[row] = yy;
        g_a[row] = yy - 2.0f * dxy + MARGIN;
    }
}

// ---------------------------------------------------------------------------
// Fused tile kernel: S-tile = x_tile @ y_tile^T, epilogue relu-sum in-place.
// Grid (64, 64); block 256 threads; each thread owns an 8x8 microtile.
// smem layout is k-major: xs[k*PAD + m], ys[k*PAD + n].
// ---------------------------------------------------------------------------
__global__ void __launch_bounds__(256, 1)
tile_kernel(const float* __restrict__ x, const float* __restrict__ y) {
    extern __shared__ float smem[];
    float* xs = smem;
    float* ys = smem + DIM * PAD;

    const int gm0 = blockIdx.y * BM;
    const int gn0 = blockIdx.x * BN;
    const int tid = threadIdx.x;

    // Load both 128x128 tiles, transposing to k-major.
    // 4096 float4 per tile / 256 threads = 16 per thread.
    #pragma unroll
    for (int it = 0; it < 16; it++) {
        int f  = tid + it * 256;          // float4 index in tile
        int r  = f >> 5;                  // row within tile (32 float4 per row)
        int c4 = f & 31;
        int k  = c4 * 4;

        float4 v = reinterpret_cast<const float4*>(x + (size_t)(gm0 + r) * DIM)[c4];
        xs[(k + 0) * PAD + r] = v.x;
        xs[(k + 1) * PAD + r] = v.y;
        xs[(k + 2) * PAD + r] = v.z;
        xs[(k + 3) * PAD + r] = v.w;

        float4 w = reinterpret_cast<const float4*>(y + (size_t)(gn0 + r) * DIM)[c4];
        ys[(k + 0) * PAD + r] = w.x;
        ys[(k + 1) * PAD + r] = w.y;
        ys[(k + 2) * PAD + r] = w.z;
        ys[(k + 3) * PAD + r] = w.w;
    }
    __syncthreads();

    const int ty = tid >> 4;   // 0..15 -> m block
    const int tx = tid & 15;   // 0..15 -> n block

    float acc[8][8];
    #pragma unroll
    for (int i = 0; i < 8; i++)
        #pragma unroll
        for (int j = 0; j < 8; j++) acc[i][j] = 0.0f;

    #pragma unroll 4
    for (int k = 0; k < DIM; k++) {
        float4 m0 = *reinterpret_cast<const float4*>(&xs[k * PAD + ty * 8]);
        float4 m1 = *reinterpret_cast<const float4*>(&xs[k * PAD + ty * 8 + 4]);
        float4 n0 = *reinterpret_cast<const float4*>(&ys[k * PAD + tx * 8]);
        float4 n1 = *reinterpret_cast<const float4*>(&ys[k * PAD + tx * 8 + 4]);
        float rm[8] = {m0.x, m0.y, m0.z, m0.w, m1.x, m1.y, m1.z, m1.w};
        float rn[8] = {n0.x, n0.y, n0.z, n0.w, n1.x, n1.y, n1.z, n1.w};
        #pragma unroll
        for (int i = 0; i < 8; i++)
            #pragma unroll
            for (int j = 0; j < 8; j++)
                acc[i][j] = fmaf(rm[i], rn[j], acc[i][j]);
    }

    // Fused epilogue: v = a[i] + 2*S - b[j]; skip diagonal; relu-sum.
    float s = 0.0f;
    #pragma unroll
    for (int mi = 0; mi < 8; mi++) {
        int   gi = gm0 + ty * 8 + mi;
        float ai = g_a[gi];
        #pragma unroll
        for (int ni = 0; ni < 8; ni++) {
            int   gj = gn0 + tx * 8 + ni;
            float v  = fmaf(2.0f, acc[mi][ni], ai - g_b[gj]);
            if (gi != gj && v > 0.0f) s += v;
        }
    }

    // Block reduction (deterministic).
    #pragma unroll
    for (int off = 16; off > 0; off >>= 1)
        s += __shfl_xor_sync(0xFFFFFFFFu, s, off);

    __shared__ float wsum[8];
    if ((tid & 31) == 0) wsum[tid >> 5] = s;
    __syncthreads();
    if (tid == 0) {
        float t = 0.0f;
        #pragma unroll
        for (int w = 0; w < 8; w++) t += wsum[w];
        g_part[blockIdx.y * NTILES + blockIdx.x] = t;
    }
}

// ---------------------------------------------------------------------------
// Final reduction: 4096 partials -> mean. Single block, deterministic.
// ---------------------------------------------------------------------------
__global__ void reduce_kernel(float* __restrict__ out) {
    __shared__ double sh[32];
    int tid = threadIdx.x;   // 1024 threads

    double s = (double)g_part[tid] + (double)g_part[tid + 1024] +
               (double)g_part[tid + 2048] + (double)g_part[tid + 3072];

    #pragma unroll
    for (int off = 16; off > 0; off >>= 1)
        s += __shfl_xor_sync(0xFFFFFFFFu, s, off);
    if ((tid & 31) == 0) sh[tid >> 5] = s;
    __syncthreads();
    if (tid == 0) {
        double t = 0.0;
        #pragma unroll
        for (int w = 0; w < 32; w++) t += sh[w];
        out[0] = (float)(t / ((double)NROWS * (double)NROWS));
    }
}

// ---------------------------------------------------------------------------
extern "C" void kernel_launch(void* const* d_in, const int* in_sizes, int n_in,
                              void* d_out, int out_size) {
    const float* x = (const float*)d_in[0];
    const float* y = (const float*)d_in[1];
    float* out = (float*)d_out;

    cudaFuncSetAttribute(tile_kernel,
                         cudaFuncAttributeMaxDynamicSharedMemorySize, SMEM_BYTES);

    precompute_kernel<<<NROWS / 8, 256>>>(x, y);
    tile_kernel<<<dim3(NTILES, NTILES), 256, SMEM_BYTES>>>(x, y);
    reduce_kernel<<<1, 1024>>>(out);
}

// round 7
// speedup vs baseline: 1.0019x; 1.0019x over previous
#include <cuda_runtime.h>
#include <cuda_bf16.h>

#define NROWS 8192
#define DIM   128
#define MARGIN 0.2f

#define BM 128
#define BN 128
#define PAD 132          // row stride in floats; 132*4=528 bytes, 16B aligned per k-row
#define NTILES 64        // 8192/128
#define SMEM_BYTES (2 * DIM * PAD * 4)

// Scratch (no allocations allowed in kernel_launch)
__device__ float g_a[NROWS];            // yy[i] - 2*<x_i,y_i> + margin
__device__ float g_b[NROWS];            // yy[j]
__device__ float g_part[NTILES * NTILES];

// ---------------------------------------------------------------------------
// Precompute a[i], b[i]. One warp per row; each lane loads one float4 (4 elems).
// ---------------------------------------------------------------------------
__global__ void precompute_kernel(const float* __restrict__ x,
                                  const float* __restrict__ y) {
    int row  = blockIdx.x * 8 + (threadIdx.x >> 5);
    int lane = threadIdx.x & 31;

    float4 xv = reinterpret_cast<const float4*>(x + (size_t)row * DIM)[lane];
    float4 yv = reinterpret_cast<const float4*>(y + (size_t)row * DIM)[lane];

    float yy  = yv.x * yv.x + yv.y * yv.y + yv.z * yv.z + yv.w * yv.w;
    float dxy = xv.x * yv.x + xv.y * yv.y + xv.z * yv.z + xv.w * yv.w;

    #pragma unroll
    for (int off = 16; off > 0; off >>= 1) {
        yy  += __shfl_xor_sync(0xFFFFFFFFu, yy,  off);
        dxy += __shfl_xor_sync(0xFFFFFFFFu, dxy, off);
    }
    if (lane == 0) {
        g_b[row] = yy;
        g_a[row] = yy - 2.0f * dxy + MARGIN;
    }
}

// ---------------------------------------------------------------------------
// Fused tile kernel: S-tile = x_tile @ y_tile^T, epilogue relu-sum in-place.
// Grid (64, 64); block 256 threads; each thread owns an 8x8 microtile.
// smem layout is k-major: xs[k*PAD + m], ys[k*PAD + n].
// ---------------------------------------------------------------------------
__global__ void __launch_bounds__(256, 1)
tile_kernel(const float* __restrict__ x, const float* __restrict__ y) {
    extern __shared__ float smem[];
    float* xs = smem;
    float* ys = smem + DIM * PAD;

    const int gm0 = blockIdx.y * BM;
    const int gn0 = blockIdx.x * BN;
    const int tid = threadIdx.x;

    // Load both 128x128 tiles, transposing to k-major.
    // 4096 float4 per tile / 256 threads = 16 per thread.
    #pragma unroll
    for (int it = 0; it < 16; it++) {
        int f  = tid + it * 256;          // float4 index in tile
        int r  = f >> 5;                  // row within tile (32 float4 per row)
        int c4 = f & 31;
        int k  = c4 * 4;

        float4 v = reinterpret_cast<const float4*>(x + (size_t)(gm0 + r) * DIM)[c4];
        xs[(k + 0) * PAD + r] = v.x;
        xs[(k + 1) * PAD + r] = v.y;
        xs[(k + 2) * PAD + r] = v.z;
        xs[(k + 3) * PAD + r] = v.w;

        float4 w = reinterpret_cast<const float4*>(y + (size_t)(gn0 + r) * DIM)[c4];
        ys[(k + 0) * PAD + r] = w.x;
        ys[(k + 1) * PAD + r] = w.y;
        ys[(k + 2) * PAD + r] = w.z;
        ys[(k + 3) * PAD + r] = w.w;
    }
    __syncthreads();

    const int ty = tid >> 4;   // 0..15 -> m block
    const int tx = tid & 15;   // 0..15 -> n block

    float acc[8][8];
    #pragma unroll
    for (int i = 0; i < 8; i++)
        #pragma unroll
        for (int j = 0; j < 8; j++) acc[i][j] = 0.0f;

    #pragma unroll 4
    for (int k = 0; k < DIM; k++) {
        float4 m0 = *reinterpret_cast<const float4*>(&xs[k * PAD + ty * 8]);
        float4 m1 = *reinterpret_cast<const float4*>(&xs[k * PAD + ty * 8 + 4]);
        float4 n0 = *reinterpret_cast<const float4*>(&ys[k * PAD + tx * 8]);
        float4 n1 = *reinterpret_cast<const float4*>(&ys[k * PAD + tx * 8 + 4]);
        float rm[8] = {m0.x, m0.y, m0.z, m0.w, m1.x, m1.y, m1.z, m1.w};
        float rn[8] = {n0.x, n0.y, n0.z, n0.w, n1.x, n1.y, n1.z, n1.w};
        #pragma unroll
        for (int i = 0; i < 8; i++)
            #pragma unroll
            for (int j = 0; j < 8; j++)
                acc[i][j] = fmaf(rm[i], rn[j], acc[i][j]);
    }

    // Fused epilogue: v = a[i] + 2*S - b[j]; skip diagonal; relu-sum.
    float s = 0.0f;
    #pragma unroll
    for (int mi = 0; mi < 8; mi++) {
        int   gi = gm0 + ty * 8 + mi;
        float ai = g_a[gi];
        #pragma unroll
        for (int ni = 0; ni < 8; ni++) {
            int   gj = gn0 + tx * 8 + ni;
            float v  = fmaf(2.0f, acc[mi][ni], ai - g_b[gj]);
            if (gi != gj && v > 0.0f) s += v;
        }
    }

    // Block reduction (deterministic).
    #pragma unroll
    for (int off = 16; off > 0; off >>= 1)
        s += __shfl_xor_sync(0xFFFFFFFFu, s, off);

    __shared__ float wsum[8];
    if ((tid & 31) == 0) wsum[tid >> 5] = s;
    __syncthreads();
    if (tid == 0) {
        float t = 0.0f;
        #pragma unroll
        for (int w = 0; w < 8; w++) t += wsum[w];
        g_part[blockIdx.y * NTILES + blockIdx.x] = t;
    }
}

// ---------------------------------------------------------------------------
// Final reduction: 4096 partials -> mean. Single block, deterministic.
// ---------------------------------------------------------------------------
__global__ void reduce_kernel(float* __restrict__ out) {
    __shared__ double sh[32];
    int tid = threadIdx.x;   // 1024 threads

    double s = (double)g_part[tid] + (double)g_part[tid + 1024] +
               (double)g_part[tid + 2048] + (double)g_part[tid + 3072];

    #pragma unroll
    for (int off = 16; off > 0; off >>= 1)
        s += __shfl_xor_sync(0xFFFFFFFFu, s, off);
    if ((tid & 31) == 0) sh[tid >> 5] = s;
    __syncthreads();
    if (tid == 0) {
        double t = 0.0;
        #pragma unroll
        for (int w = 0; w < 32; w++) t += sh[w];
        out[0] = (float)(t / ((double)NROWS * (double)NROWS));
    }
}

// ---------------------------------------------------------------------------
extern "C" void kernel_launch(void* const* d_in, const int* in_sizes, int n_in,
                              void* d_out, int out_size) {
    const float* x = (const float*)d_in[0];
    const float* y = (const float*)d_in[1];
    float* out = (float*)d_out;

    cudaFuncSetAttribute(tile_kernel,
                         cudaFuncAttributeMaxDynamicSharedMemorySize, SMEM_BYTES);

    precompute_kernel<<<NROWS / 8, 256>>>(x, y);
    tile_kernel<<<dim3(NTILES, NTILES), 256, SMEM_BYTES>>>(x, y);
    reduce_kernel<<<1, 1024>>>(out);
}

// round 9
// speedup vs baseline: 4.1278x; 4.1197x over previous
#include <cuda_runtime.h>
#include <cuda_bf16.h>
#include <cstdint>

#define NROWS 8192
#define DIM   128
#define MARGIN 0.2f

#define BM 128
#define BN 128
#define KB 256              // bf16 K: [0,128)=hi, [128,256)=lo
#define NT 64               // 8192/128

// smem layout (bytes): A 64KB | B 64KB | a_sh 512B | b_sh 512B | wsum
#define A_OFF    0
#define B_OFF    65536
#define ASH_OFF  131072
#define BSH_OFF  131584
#define WSUM_OFF 132096
#define SMEM_TOTAL 132160

// device scratch
__device__ float g_a[NROWS];                                   // yy[i]-2<x_i,y_i>+margin
__device__ float g_b[NROWS];                                   // yy[j]
__device__ float g_part[NT * NT];
__device__ __align__(16) __nv_bfloat16 g_xs[NROWS * KB];       // [row][hi|lo]
__device__ __align__(16) __nv_bfloat16 g_ys[NROWS * KB];

__device__ __forceinline__ uint32_t smem_u32(const void* p) {
    uint32_t a;
    asm("{ .reg .u64 t; cvta.to.shared.u64 t, %1; cvt.u32.u64 %0, t; }" : "=r"(a) : "l"(p));
    return a;
}

#define LDSM4(r, addr) \
    asm volatile("ldmatrix.sync.aligned.m8n8.x4.shared.b16 {%0,%1,%2,%3}, [%4];" \
        : "=r"((r)[0]), "=r"((r)[1]), "=r"((r)[2]), "=r"((r)[3]) : "r"(addr))

__device__ __forceinline__ void mma16816(float* c, const uint32_t* a,
                                         uint32_t b0, uint32_t b1) {
    asm volatile(
        "mma.sync.aligned.m16n8k16.row.col.f32.bf16.bf16.f32 "
        "{%0,%1,%2,%3}, {%4,%5,%6,%7}, {%8,%9}, {%0,%1,%2,%3};"
        : "+f"(c[0]), "+f"(c[1]), "+f"(c[2]), "+f"(c[3])
        : "r"(a[0]), "r"(a[1]), "r"(a[2]), "r"(a[3]), "r"(b0), "r"(b1));
}

// ---------------------------------------------------------------------------
// Precompute a[i], b[i] and bf16 hi/lo split rows. One warp per row.
// ---------------------------------------------------------------------------
__global__ void precompute_kernel(const float* __restrict__ x,
                                  const float* __restrict__ y) {
    int row  = blockIdx.x * 8 + (threadIdx.x >> 5);
    int lane = threadIdx.x & 31;

    float4 xv = reinterpret_cast<const float4*>(x + (size_t)row * DIM)[lane];
    float4 yv = reinterpret_cast<const float4*>(y + (size_t)row * DIM)[lane];

    float yy  = yv.x * yv.x + yv.y * yv.y + yv.z * yv.z + yv.w * yv.w;
    float dxy = xv.x * yv.x + xv.y * yv.y + xv.z * yv.z + xv.w * yv.w;

    __nv_bfloat16* xr = g_xs + (size_t)row * KB;
    __nv_bfloat16* yr = g_ys + (size_t)row * KB;
    float xe[4] = {xv.x, xv.y, xv.z, xv.w};
    float ye[4] = {yv.x, yv.y, yv.z, yv.w};
    #pragma unroll
    for (int j = 0; j < 4; j++) {
        __nv_bfloat16 xh = __float2bfloat16(xe[j]);
        __nv_bfloat16 xl = __float2bfloat16(xe[j] - __bfloat162float(xh));
        __nv_bfloat16 yh = __float2bfloat16(ye[j]);
        __nv_bfloat16 yl = __float2bfloat16(ye[j] - __bfloat162float(yh));
        xr[lane * 4 + j]       = xh;
        xr[128 + lane * 4 + j] = xl;
        yr[lane * 4 + j]       = yh;
        yr[128 + lane * 4 + j] = yl;
    }

    #pragma unroll
    for (int off = 16; off > 0; off >>= 1) {
        yy  += __shfl_xor_sync(0xFFFFFFFFu, yy,  off);
        dxy += __shfl_xor_sync(0xFFFFFFFFu, dxy, off);
    }
    if (lane == 0) {
        g_b[row] = yy;
        g_a[row] = yy - 2.0f * dxy + MARGIN;
    }
}

// ---------------------------------------------------------------------------
// Tile kernel: 128x128 tile, K=256 bf16 (hi|lo concat => hh+hl+lh+ll products).
// 8 warps (2m x 4n), warp tile 64x32, mma.sync m16n8k16, epilogue on regs.
// ---------------------------------------------------------------------------
__global__ void __launch_bounds__(256, 1)
tile_kernel() {
    extern __shared__ char smem[];
    const uint32_t sb = smem_u32(smem);
    const int tid  = threadIdx.x;
    const int wid  = tid >> 5;
    const int lane = tid & 31;
    const int wm   = wid >> 2;         // 0..1
    const int wn   = wid & 3;          // 0..3
    const int gm0  = blockIdx.y * BM;
    const int gn0  = blockIdx.x * BN;

    // ---- load tiles: 128 rows x 512B each, XOR-swizzled 16B chunks ----
    // chunk addr(r, c) = r*512 + ((c ^ (r&7)) << 4)
    #pragma unroll
    for (int it = 0; it < 16; it++) {
        int f = it * 256 + tid;
        int r = f >> 5, c = f & 31;
        uint32_t off = (uint32_t)(r * 512 + ((c ^ (r & 7)) << 4));
        uint4 v = reinterpret_cast<const uint4*>(g_xs + (size_t)(gm0 + r) * KB)[c];
        *reinterpret_cast<uint4*>(smem + A_OFF + off) = v;
        uint4 w = reinterpret_cast<const uint4*>(g_ys + (size_t)(gn0 + r) * KB)[c];
        *reinterpret_cast<uint4*>(smem + B_OFF + off) = w;
    }
    float* a_sh = reinterpret_cast<float*>(smem + ASH_OFF);
    float* b_sh = reinterpret_cast<float*>(smem + BSH_OFF);
    if (tid < 128) {
        a_sh[tid] = g_a[gm0 + tid];
        b_sh[tid] = g_b[gn0 + tid];
    }
    __syncthreads();

    // ---- mainloop ----
    float acc[4][4][4];
    #pragma unroll
    for (int i = 0; i < 4; i++)
        #pragma unroll
        for (int j = 0; j < 4; j++)
            #pragma unroll
            for (int q = 0; q < 4; q++) acc[i][j][q] = 0.0f;

    // ldmatrix lane addressing
    const int a_row  = wm * 64 + ((lane >> 3) & 1) * 8 + (lane & 7);
    const int a_kcl  = lane >> 4;            // 0/1 : k-chunk select
    const int b_row  = wn * 32 + ((lane >> 4) & 1) * 8 + (lane & 7);
    const int b_kcl  = (lane >> 3) & 1;

    #pragma unroll
    for (int ks = 0; ks < 16; ks++) {
        uint32_t af[4][4], bfr[2][4];
        #pragma unroll
        for (int mi = 0; mi < 4; mi++) {
            int m  = a_row + mi * 16;
            int kc = 2 * ks + a_kcl;
            uint32_t addr = sb + A_OFF + (uint32_t)(m * 512 + ((kc ^ (m & 7)) << 4));
            LDSM4(af[mi], addr);
        }
        #pragma unroll
        for (int nb = 0; nb < 2; nb++) {
            int n  = b_row + nb * 16;
            int kc = 2 * ks + b_kcl;
            uint32_t addr = sb + B_OFF + (uint32_t)(n * 512 + ((kc ^ (n & 7)) << 4));
            LDSM4(bfr[nb], addr);
        }
        #pragma unroll
        for (int mi = 0; mi < 4; mi++) {
            #pragma unroll
            for (int nb = 0; nb < 2; nb++) {
                mma16816(acc[mi][2 * nb + 0], af[mi], bfr[nb][0], bfr[nb][1]);
                mma16816(acc[mi][2 * nb + 1], af[mi], bfr[nb][2], bfr[nb][3]);
            }
        }
    }

    // ---- epilogue directly on register fragments ----
    // D frag lane map: c0:(m=g, n=tg*2) c1:(g, tg*2+1) c2:(g+8, tg*2) c3:(g+8, tg*2+1)
    const int g  = lane >> 2;
    const int tg = lane & 3;
    float s = 0.0f;
    #pragma unroll
    for (int mi = 0; mi < 4; mi++) {
        int m0 = wm * 64 + mi * 16 + g;          // local row (and m0+8)
        float a0 = a_sh[m0], a1 = a_sh[m0 + 8];
        int gi0 = gm0 + m0, gi1 = gi0 + 8;
        #pragma unroll
        for (int ni = 0; ni < 4; ni++) {
            int n0 = wn * 32 + ni * 8 + tg * 2;
            float b0 = b_sh[n0], b1 = b_sh[n0 + 1];
            int gj0 = gn0 + n0, gj1 = gj0 + 1;
            float v;
            v = fmaf(2.0f, acc[mi][ni][0], a0 - b0); if (gi0 != gj0 && v > 0.0f) s += v;
            v = fmaf(2.0f, acc[mi][ni][1], a0 - b1); if (gi0 != gj1 && v > 0.0f) s += v;
            v = fmaf(2.0f, acc[mi][ni][2], a1 - b0); if (gi1 != gj0 && v > 0.0f) s += v;
            v = fmaf(2.0f, acc[mi][ni][3], a1 - b1); if (gi1 != gj1 && v > 0.0f) s += v;
        }
    }

    // ---- deterministic block reduction ----
    #pragma unroll
    for (int off = 16; off > 0; off >>= 1)
        s += __shfl_xor_sync(0xFFFFFFFFu, s, off);
    float* wsum = reinterpret_cast<float*>(smem + WSUM_OFF);
    if (lane == 0) wsum[wid] = s;
    __syncthreads();
    if (tid == 0) {
        float t = 0.0f;
        #pragma unroll
        for (int w = 0; w < 8; w++) t += wsum[w];
        g_part[blockIdx.y * NT + blockIdx.x] = t;
    }
}

// ---------------------------------------------------------------------------
// Final reduction: 4096 partials -> mean. Deterministic.
// ---------------------------------------------------------------------------
__global__ void reduce_kernel(float* __restrict__ out) {
    __shared__ double sh[32];
    int tid = threadIdx.x;   // 1024 threads

    double s = (double)g_part[tid] + (double)g_part[tid + 1024] +
               (double)g_part[tid + 2048] + (double)g_part[tid + 3072];

    #pragma unroll
    for (int off = 16; off > 0; off >>= 1)
        s += __shfl_xor_sync(0xFFFFFFFFu, s, off);
    if ((tid & 31) == 0) sh[tid >> 5] = s;
    __syncthreads();
    if (tid == 0) {
        double t = 0.0;
        #pragma unroll
        for (int w = 0; w < 32; w++) t += sh[w];
        out[0] = (float)(t / ((double)NROWS * (double)NROWS));
    }
}

// ---------------------------------------------------------------------------
extern "C" void kernel_launch(void* const* d_in, const int* in_sizes, int n_in,
                              void* d_out, int out_size) {
    const float* x = (const float*)d_in[0];
    const float* y = (const float*)d_in[1];
    float* out = (float*)d_out;

    cudaFuncSetAttribute(tile_kernel,
                         cudaFuncAttributeMaxDynamicSharedMemorySize, SMEM_TOTAL);

    precompute_kernel<<<NROWS / 8, 256>>>(x, y);
    tile_kernel<<<dim3(NT, NT), 256, SMEM_TOTAL>>>();
    reduce_kernel<<<1, 1024>>>(out);
}

// round 10
// speedup vs baseline: 6.3162x; 1.5302x over previous
#include <cuda_runtime.h>
#include <cuda_bf16.h>
#include <cstdint>

#define NROWS 8192
#define DIM   128
#define MARGIN 0.2f

#define BM 128
#define BN 128
#define KB 256              // bf16 K per row: [0,128)=hi, [128,256)=lo
#define NT 64               // 8192/128

#define NCHUNK 4            // K chunks of 64 bf16 (128B per row)
#define NSTAGE 3
#define STAGE_BYTES 32768   // A 16KB + B 16KB
#define BSTG 16384          // B offset within a stage

#define ASH_OFF  (NSTAGE * STAGE_BYTES)       // 98304
#define BSH_OFF  (ASH_OFF + 512)
#define WSUM_OFF (ASH_OFF + 1024)
#define SMEM_TOTAL (ASH_OFF + 1056)

// device scratch
__device__ float g_a[NROWS];                                   // yy[i]-2<x_i,y_i>+margin
__device__ float g_b[NROWS];                                   // yy[j]
__device__ float g_part[NT * NT];
__device__ __align__(16) __nv_bfloat16 g_xs[NROWS * KB];       // [row][hi|lo]
__device__ __align__(16) __nv_bfloat16 g_ys[NROWS * KB];

__device__ __forceinline__ uint32_t smem_u32(const void* p) {
    uint32_t a;
    asm("{ .reg .u64 t; cvta.to.shared.u64 t, %1; cvt.u32.u64 %0, t; }" : "=r"(a) : "l"(p));
    return a;
}
__device__ __forceinline__ void cp16(uint32_t dst, const void* src) {
    asm volatile("cp.async.cg.shared.global [%0], [%1], 16;" :: "r"(dst), "l"(src));
}
#define CP_COMMIT() asm volatile("cp.async.commit_group;" ::: "memory")
#define CP_WAIT(n)  asm volatile("cp.async.wait_group %0;" :: "n"(n) : "memory")

#define LDSM4(r, addr) \
    asm volatile("ldmatrix.sync.aligned.m8n8.x4.shared.b16 {%0,%1,%2,%3}, [%4];" \
        : "=r"((r)[0]), "=r"((r)[1]), "=r"((r)[2]), "=r"((r)[3]) : "r"(addr))

__device__ __forceinline__ void mma16816(float* c, const uint32_t* a,
                                         uint32_t b0, uint32_t b1) {
    asm volatile(
        "mma.sync.aligned.m16n8k16.row.col.f32.bf16.bf16.f32 "
        "{%0,%1,%2,%3}, {%4,%5,%6,%7}, {%8,%9}, {%0,%1,%2,%3};"
        : "+f"(c[0]), "+f"(c[1]), "+f"(c[2]), "+f"(c[3])
        : "r"(a[0]), "r"(a[1]), "r"(a[2]), "r"(a[3]), "r"(b0), "r"(b1));
}

// ---------------------------------------------------------------------------
// Precompute a[i], b[i] and bf16 hi/lo split rows. One warp per row.
// ---------------------------------------------------------------------------
__global__ void precompute_kernel(const float* __restrict__ x,
                                  const float* __restrict__ y) {
    int row  = blockIdx.x * 8 + (threadIdx.x >> 5);
    int lane = threadIdx.x & 31;

    float4 xv = reinterpret_cast<const float4*>(x + (size_t)row * DIM)[lane];
    float4 yv = reinterpret_cast<const float4*>(y + (size_t)row * DIM)[lane];

    float yy  = yv.x * yv.x + yv.y * yv.y + yv.z * yv.z + yv.w * yv.w;
    float dxy = xv.x * yv.x + xv.y * yv.y + xv.z * yv.z + xv.w * yv.w;

    __nv_bfloat16* xr = g_xs + (size_t)row * KB;
    __nv_bfloat16* yr = g_ys + (size_t)row * KB;
    float xe[4] = {xv.x, xv.y, xv.z, xv.w};
    float ye[4] = {yv.x, yv.y, yv.z, yv.w};
    #pragma unroll
    for (int j = 0; j < 4; j++) {
        __nv_bfloat16 xh = __float2bfloat16(xe[j]);
        __nv_bfloat16 xl = __float2bfloat16(xe[j] - __bfloat162float(xh));
        __nv_bfloat16 yh = __float2bfloat16(ye[j]);
        __nv_bfloat16 yl = __float2bfloat16(ye[j] - __bfloat162float(yh));
        xr[lane * 4 + j]       = xh;
        xr[128 + lane * 4 + j] = xl;
        yr[lane * 4 + j]       = yh;
        yr[128 + lane * 4 + j] = yl;
    }

    #pragma unroll
    for (int off = 16; off > 0; off >>= 1) {
        yy  += __shfl_xor_sync(0xFFFFFFFFu, yy,  off);
        dxy += __shfl_xor_sync(0xFFFFFFFFu, dxy, off);
    }
    if (lane == 0) {
        g_b[row] = yy;
        g_a[row] = yy - 2.0f * dxy + MARGIN;
    }
}

// ---------------------------------------------------------------------------
// Tile kernel: 128x128 tile, K=256 bf16 streamed in 4 chunks via a 3-stage
// cp.async ring. 8 warps (2m x 4n), warp tile 64x32, mma.sync m16n8k16,
// epilogue on register fragments. 2 CTAs/SM.
// ---------------------------------------------------------------------------
struct TileCtx {
    uint32_t sb;
    int tid, gm0, gn0;
    int a_row, a_kcl, b_row, b_kcl;
};

__device__ __forceinline__ void load_chunk(const TileCtx& c, int chunk, int stage) {
    const uint32_t abase = c.sb + stage * STAGE_BYTES;
    #pragma unroll
    for (int i = 0; i < 4; i++) {
        int f = i * 256 + c.tid;
        int r = f >> 3, cc = f & 7;
        uint32_t off = (uint32_t)(r * 128 + ((cc ^ (r & 7)) << 4));
        cp16(abase + off,        g_xs + (size_t)(c.gm0 + r) * KB + chunk * 64 + cc * 8);
        cp16(abase + BSTG + off, g_ys + (size_t)(c.gn0 + r) * KB + chunk * 64 + cc * 8);
    }
    CP_COMMIT();
}

__device__ __forceinline__ void compute_chunk(const TileCtx& c, int stage,
                                              float (&acc)[4][4][4]) {
    const uint32_t abase = c.sb + stage * STAGE_BYTES;
    #pragma unroll
    for (int s = 0; s < 4; s++) {
        uint32_t af[4][4], bfr[2][4];
        #pragma unroll
        for (int mi = 0; mi < 4; mi++) {
            int m  = c.a_row + mi * 16;
            int kc = 2 * s + c.a_kcl;
            LDSM4(af[mi], abase + (uint32_t)(m * 128 + ((kc ^ (m & 7)) << 4)));
        }
        #pragma unroll
        for (int nb = 0; nb < 2; nb++) {
            int n  = c.b_row + nb * 16;
            int kc = 2 * s + c.b_kcl;
            LDSM4(bfr[nb], abase + BSTG + (uint32_t)(n * 128 + ((kc ^ (n & 7)) << 4)));
        }
        #pragma unroll
        for (int mi = 0; mi < 4; mi++) {
            #pragma unroll
            for (int nb = 0; nb < 2; nb++) {
                mma16816(acc[mi][2 * nb + 0], af[mi], bfr[nb][0], bfr[nb][1]);
                mma16816(acc[mi][2 * nb + 1], af[mi], bfr[nb][2], bfr[nb][3]);
            }
        }
    }
}

__global__ void __launch_bounds__(256, 2)
tile_kernel() {
    extern __shared__ char smem[];
    const int tid  = threadIdx.x;
    const int wid  = tid >> 5;
    const int lane = tid & 31;
    const int wm   = wid >> 2;         // 0..1
    const int wn   = wid & 3;          // 0..3

    TileCtx c;
    c.sb    = smem_u32(smem);
    c.tid   = tid;
    c.gm0   = blockIdx.y * BM;
    c.gn0   = blockIdx.x * BN;
    c.a_row = wm * 64 + ((lane >> 3) & 1) * 8 + (lane & 7);
    c.a_kcl = lane >> 4;
    c.b_row = wn * 32 + ((lane >> 4) & 1) * 8 + (lane & 7);
    c.b_kcl = (lane >> 3) & 1;

    // prologue: fill the 3-stage ring
    load_chunk(c, 0, 0);
    load_chunk(c, 1, 1);
    load_chunk(c, 2, 2);

    float* a_sh = reinterpret_cast<float*>(smem + ASH_OFF);
    float* b_sh = reinterpret_cast<float*>(smem + BSH_OFF);
    if (tid < 128) {
        a_sh[tid] = g_a[c.gm0 + tid];
        b_sh[tid] = g_b[c.gn0 + tid];
    }

    float acc[4][4][4];
    #pragma unroll
    for (int i = 0; i < 4; i++)
        #pragma unroll
        for (int j = 0; j < 4; j++)
            #pragma unroll
            for (int q = 0; q < 4; q++) acc[i][j][q] = 0.0f;

    // chunk 0
    CP_WAIT(2);
    __syncthreads();
    compute_chunk(c, 0, acc);
    __syncthreads();                 // all warps done reading stage 0
    load_chunk(c, 3, 0);             // reuse stage 0 for chunk 3

    // chunk 1
    CP_WAIT(2);
    __syncthreads();
    compute_chunk(c, 1, acc);

    // chunk 2
    CP_WAIT(1);
    __syncthreads();
    compute_chunk(c, 2, acc);

    // chunk 3
    CP_WAIT(0);
    __syncthreads();
    compute_chunk(c, 0, acc);

    // ---- epilogue directly on register fragments ----
    const int g  = lane >> 2;
    const int tg = lane & 3;
    float s = 0.0f;
    #pragma unroll
    for (int mi = 0; mi < 4; mi++) {
        int m0 = wm * 64 + mi * 16 + g;
        float a0 = a_sh[m0], a1 = a_sh[m0 + 8];
        int gi0 = c.gm0 + m0, gi1 = gi0 + 8;
        #pragma unroll
        for (int ni = 0; ni < 4; ni++) {
            int n0 = wn * 32 + ni * 8 + tg * 2;
            float b0 = b_sh[n0], b1 = b_sh[n0 + 1];
            int gj0 = c.gn0 + n0, gj1 = gj0 + 1;
            float v;
            v = fmaf(2.0f, acc[mi][ni][0], a0 - b0); if (gi0 != gj0 && v > 0.0f) s += v;
            v = fmaf(2.0f, acc[mi][ni][1], a0 - b1); if (gi0 != gj1 && v > 0.0f) s += v;
            v = fmaf(2.0f, acc[mi][ni][2], a1 - b0); if (gi1 != gj0 && v > 0.0f) s += v;
            v = fmaf(2.0f, acc[mi][ni][3], a1 - b1); if (gi1 != gj1 && v > 0.0f) s += v;
        }
    }

    // ---- deterministic block reduction ----
    #pragma unroll
    for (int off = 16; off > 0; off >>= 1)
        s += __shfl_xor_sync(0xFFFFFFFFu, s, off);
    float* wsum = reinterpret_cast<float*>(smem + WSUM_OFF);
    if (lane == 0) wsum[wid] = s;
    __syncthreads();
    if (tid == 0) {
        float t = 0.0f;
        #pragma unroll
        for (int w = 0; w < 8; w++) t += wsum[w];
        g_part[blockIdx.y * NT + blockIdx.x] = t;
    }
}

// ---------------------------------------------------------------------------
// Final reduction: 4096 partials -> mean. Deterministic.
// ---------------------------------------------------------------------------
__global__ void reduce_kernel(float* __restrict__ out) {
    __shared__ double sh[32];
    int tid = threadIdx.x;   // 1024 threads

    double s = (double)g_part[tid] + (double)g_part[tid + 1024] +
               (double)g_part[tid + 2048] + (double)g_part[tid + 3072];

    #pragma unroll
    for (int off = 16; off > 0; off >>= 1)
        s += __shfl_xor_sync(0xFFFFFFFFu, s, off);
    if ((tid & 31) == 0) sh[tid >> 5] = s;
    __syncthreads();
    if (tid == 0) {
        double t = 0.0;
        #pragma unroll
        for (int w = 0; w < 32; w++) t += sh[w];
        out[0] = (float)(t / ((double)NROWS * (double)NROWS));
    }
}

// ---------------------------------------------------------------------------
extern "C" void kernel_launch(void* const* d_in, const int* in_sizes, int n_in,
                              void* d_out, int out_size) {
    const float* x = (const float*)d_in[0];
    const float* y = (const float*)d_in[1];
    float* out = (float*)d_out;

    cudaFuncSetAttribute(tile_kernel,
                         cudaFuncAttributeMaxDynamicSharedMemorySize, SMEM_TOTAL);

    precompute_kernel<<<NROWS / 8, 256>>>(x, y);
    tile_kernel<<<dim3(NT, NT), 256, SMEM_TOTAL>>>();
    reduce_kernel<<<1, 1024>>>(out);
}

// round 11
// speedup vs baseline: 9.0742x; 1.4367x over previous
#include <cuda_runtime.h>
#include <cuda_bf16.h>
#include <cstdint>

#define NROWS 8192
#define DIM   128
#define MARGIN 0.2f

#define BM 128
#define BN 128
#define KB 128              // bf16 K per row (pure hi; lo contributes nothing)
#define NT 64               // 8192/128

#define NSTAGE 2
#define STAGE_BYTES 32768   // A 16KB + B 16KB (64 cols x 128 rows x 2B each)
#define BSTG 16384          // B offset within a stage

#define ASH_OFF  (NSTAGE * STAGE_BYTES)       // 65536
#define BSH_OFF  (ASH_OFF + 512)
#define WSUM_OFF (ASH_OFF + 1024)
#define SMEM_TOTAL (ASH_OFF + 1056)

// device scratch
__device__ float g_a[NROWS];                                   // yy[i]-2<x_i,y_i>+margin
__device__ float g_b[NROWS];                                   // yy[j]
__device__ float g_part[NT * NT];
__device__ __align__(16) __nv_bfloat16 g_xs[NROWS * KB];
__device__ __align__(16) __nv_bfloat16 g_ys[NROWS * KB];

__device__ __forceinline__ uint32_t smem_u32(const void* p) {
    uint32_t a;
    asm("{ .reg .u64 t; cvta.to.shared.u64 t, %1; cvt.u32.u64 %0, t; }" : "=r"(a) : "l"(p));
    return a;
}
__device__ __forceinline__ void cp16(uint32_t dst, const void* src) {
    asm volatile("cp.async.cg.shared.global [%0], [%1], 16;" :: "r"(dst), "l"(src));
}
#define CP_COMMIT() asm volatile("cp.async.commit_group;" ::: "memory")
#define CP_WAIT(n)  asm volatile("cp.async.wait_group %0;" :: "n"(n) : "memory")

#define LDSM4(r, addr) \
    asm volatile("ldmatrix.sync.aligned.m8n8.x4.shared.b16 {%0,%1,%2,%3}, [%4];" \
        : "=r"((r)[0]), "=r"((r)[1]), "=r"((r)[2]), "=r"((r)[3]) : "r"(addr))

__device__ __forceinline__ void mma16816(float* c, const uint32_t* a,
                                         uint32_t b0, uint32_t b1) {
    asm volatile(
        "mma.sync.aligned.m16n8k16.row.col.f32.bf16.bf16.f32 "
        "{%0,%1,%2,%3}, {%4,%5,%6,%7}, {%8,%9}, {%0,%1,%2,%3};"
        : "+f"(c[0]), "+f"(c[1]), "+f"(c[2]), "+f"(c[3])
        : "r"(a[0]), "r"(a[1]), "r"(a[2]), "r"(a[3]), "r"(b0), "r"(b1));
}

// ---------------------------------------------------------------------------
// Precompute a[i], b[i] and bf16 rows. One warp per row.
// ---------------------------------------------------------------------------
__global__ void precompute_kernel(const float* __restrict__ x,
                                  const float* __restrict__ y) {
    int row  = blockIdx.x * 8 + (threadIdx.x >> 5);
    int lane = threadIdx.x & 31;

    float4 xv = reinterpret_cast<const float4*>(x + (size_t)row * DIM)[lane];
    float4 yv = reinterpret_cast<const float4*>(y + (size_t)row * DIM)[lane];

    float yy  = yv.x * yv.x + yv.y * yv.y + yv.z * yv.z + yv.w * yv.w;
    float dxy = xv.x * yv.x + xv.y * yv.y + xv.z * yv.z + xv.w * yv.w;

    // bf16 conversion, 4 elems -> 2 packed words each
    __nv_bfloat162* xr = reinterpret_cast<__nv_bfloat162*>(g_xs + (size_t)row * KB);
    __nv_bfloat162* yr = reinterpret_cast<__nv_bfloat162*>(g_ys + (size_t)row * KB);
    xr[lane * 2 + 0] = __floats2bfloat162_rn(xv.x, xv.y);
    xr[lane * 2 + 1] = __floats2bfloat162_rn(xv.z, xv.w);
    yr[lane * 2 + 0] = __floats2bfloat162_rn(yv.x, yv.y);
    yr[lane * 2 + 1] = __floats2bfloat162_rn(yv.z, yv.w);

    #pragma unroll
    for (int off = 16; off > 0; off >>= 1) {
        yy  += __shfl_xor_sync(0xFFFFFFFFu, yy,  off);
        dxy += __shfl_xor_sync(0xFFFFFFFFu, dxy, off);
    }
    if (lane == 0) {
        g_b[row] = yy;
        g_a[row] = yy - 2.0f * dxy + MARGIN;
    }
}

// ---------------------------------------------------------------------------
// Tile kernel: 128x128 tile, K=128 bf16, 2 chunks of 64 via 2-stage cp.async.
// 8 warps (2m x 4n), warp tile 64x32, mma.sync m16n8k16, epilogue on regs.
// 2 CTAs/SM.
// ---------------------------------------------------------------------------
struct TileCtx {
    uint32_t sb;
    int tid, gm0, gn0;
    int a_row, a_kcl, b_row, b_kcl;
};

__device__ __forceinline__ void load_chunk(const TileCtx& c, int chunk, int stage) {
    const uint32_t abase = c.sb + stage * STAGE_BYTES;
    #pragma unroll
    for (int i = 0; i < 4; i++) {
        int f = i * 256 + c.tid;
        int r = f >> 3, cc = f & 7;
        uint32_t off = (uint32_t)(r * 128 + ((cc ^ (r & 7)) << 4));
        cp16(abase + off,        g_xs + (size_t)(c.gm0 + r) * KB + chunk * 64 + cc * 8);
        cp16(abase + BSTG + off, g_ys + (size_t)(c.gn0 + r) * KB + chunk * 64 + cc * 8);
    }
    CP_COMMIT();
}

__device__ __forceinline__ void compute_chunk(const TileCtx& c, int stage,
                                              float (&acc)[4][4][4]) {
    const uint32_t abase = c.sb + stage * STAGE_BYTES;
    #pragma unroll
    for (int s = 0; s < 4; s++) {
        uint32_t af[4][4], bfr[2][4];
        #pragma unroll
        for (int mi = 0; mi < 4; mi++) {
            int m  = c.a_row + mi * 16;
            int kc = 2 * s + c.a_kcl;
            LDSM4(af[mi], abase + (uint32_t)(m * 128 + ((kc ^ (m & 7)) << 4)));
        }
        #pragma unroll
        for (int nb = 0; nb < 2; nb++) {
            int n  = c.b_row + nb * 16;
            int kc = 2 * s + c.b_kcl;
            LDSM4(bfr[nb], abase + BSTG + (uint32_t)(n * 128 + ((kc ^ (n & 7)) << 4)));
        }
        #pragma unroll
        for (int mi = 0; mi < 4; mi++) {
            #pragma unroll
            for (int nb = 0; nb < 2; nb++) {
                mma16816(acc[mi][2 * nb + 0], af[mi], bfr[nb][0], bfr[nb][1]);
                mma16816(acc[mi][2 * nb + 1], af[mi], bfr[nb][2], bfr[nb][3]);
            }
        }
    }
}

__global__ void __launch_bounds__(256, 2)
tile_kernel() {
    extern __shared__ char smem[];
    const int tid  = threadIdx.x;
    const int wid  = tid >> 5;
    const int lane = tid & 31;
    const int wm   = wid >> 2;         // 0..1
    const int wn   = wid & 3;          // 0..3

    TileCtx c;
    c.sb    = smem_u32(smem);
    c.tid   = tid;
    c.gm0   = blockIdx.y * BM;
    c.gn0   = blockIdx.x * BN;
    c.a_row = wm * 64 + ((lane >> 3) & 1) * 8 + (lane & 7);
    c.a_kcl = lane >> 4;
    c.b_row = wn * 32 + ((lane >> 4) & 1) * 8 + (lane & 7);
    c.b_kcl = (lane >> 3) & 1;

    load_chunk(c, 0, 0);
    load_chunk(c, 1, 1);

    float* a_sh = reinterpret_cast<float*>(smem + ASH_OFF);
    float* b_sh = reinterpret_cast<float*>(smem + BSH_OFF);
    if (tid < 128) {
        a_sh[tid] = g_a[c.gm0 + tid];
        b_sh[tid] = g_b[c.gn0 + tid];
    }

    float acc[4][4][4];
    #pragma unroll
    for (int i = 0; i < 4; i++)
        #pragma unroll
        for (int j = 0; j < 4; j++)
            #pragma unroll
            for (int q = 0; q < 4; q++) acc[i][j][q] = 0.0f;

    CP_WAIT(1);
    __syncthreads();
    compute_chunk(c, 0, acc);

    CP_WAIT(0);
    __syncthreads();
    compute_chunk(c, 1, acc);

    // ---- epilogue directly on register fragments ----
    const int g  = lane >> 2;
    const int tg = lane & 3;
    float s = 0.0f;
    #pragma unroll
    for (int mi = 0; mi < 4; mi++) {
        int m0 = wm * 64 + mi * 16 + g;
        float a0 = a_sh[m0], a1 = a_sh[m0 + 8];
        int gi0 = c.gm0 + m0, gi1 = gi0 + 8;
        #pragma unroll
        for (int ni = 0; ni < 4; ni++) {
            int n0 = wn * 32 + ni * 8 + tg * 2;
            float b0 = b_sh[n0], b1 = b_sh[n0 + 1];
            int gj0 = c.gn0 + n0, gj1 = gj0 + 1;
            float v;
            v = fmaf(2.0f, acc[mi][ni][0], a0 - b0); if (gi0 != gj0 && v > 0.0f) s += v;
            v = fmaf(2.0f, acc[mi][ni][1], a0 - b1); if (gi0 != gj1 && v > 0.0f) s += v;
            v = fmaf(2.0f, acc[mi][ni][2], a1 - b0); if (gi1 != gj0 && v > 0.0f) s += v;
            v = fmaf(2.0f, acc[mi][ni][3], a1 - b1); if (gi1 != gj1 && v > 0.0f) s += v;
        }
    }

    // ---- deterministic block reduction ----
    #pragma unroll
    for (int off = 16; off > 0; off >>= 1)
        s += __shfl_xor_sync(0xFFFFFFFFu, s, off);
    float* wsum = reinterpret_cast<float*>(smem + WSUM_OFF);
    if (lane == 0) wsum[wid] = s;
    __syncthreads();
    if (tid == 0) {
        float t = 0.0f;
        #pragma unroll
        for (int w = 0; w < 8; w++) t += wsum[w];
        g_part[blockIdx.y * NT + blockIdx.x] = t;
    }
}

// ---------------------------------------------------------------------------
// Final reduction: 4096 partials -> mean. Deterministic.
// ---------------------------------------------------------------------------
__global__ void reduce_kernel(float* __restrict__ out) {
    __shared__ double sh[32];
    int tid = threadIdx.x;   // 1024 threads

    double s = (double)g_part[tid] + (double)g_part[tid + 1024] +
               (double)g_part[tid + 2048] + (double)g_part[tid + 3072];

    #pragma unroll
    for (int off = 16; off > 0; off >>= 1)
        s += __shfl_xor_sync(0xFFFFFFFFu, s, off);
    if ((tid & 31) == 0) sh[tid >> 5] = s;
    __syncthreads();
    if (tid == 0) {
        double t = 0.0;
        #pragma unroll
        for (int w = 0; w < 32; w++) t += sh[w];
        out[0] = (float)(t / ((double)NROWS * (double)NROWS));
    }
}

// ---------------------------------------------------------------------------
extern "C" void kernel_launch(void* const* d_in, const int* in_sizes, int n_in,
                              void* d_out, int out_size) {
    const float* x = (const float*)d_in[0];
    const float* y = (const float*)d_in[1];
    float* out = (float*)d_out;

    cudaFuncSetAttribute(tile_kernel,
                         cudaFuncAttributeMaxDynamicSharedMemorySize, SMEM_TOTAL);

    precompute_kernel<<<NROWS / 8, 256>>>(x, y);
    tile_kernel<<<dim3(NT, NT), 256, SMEM_TOTAL>>>();
    reduce_kernel<<<1, 1024>>>(out);
}